// round 4
// baseline (speedup 1.0000x reference)
#include <cuda_runtime.h>
#include <cstdint>

// EnsembleRBF: out[m,n,d] = sum_c exp(-||x_n - c_c||^2) * sigma^2 * W[m,c,d]
// N=100000, C=256, D=2, M=5, sigma=0.25
//
// R4: 4-way C-split by warp (grid 1563, 3x warps), zero-MOV ulonglong2 smem
// tables (pre-packed f32x2 operands), 4 broadcast LDS.128 per iteration.

#define C_CENTERS 256
#define M_MODELS 5
#define TPB 128
#define PAIRS_PER_BLOCK 32
#define QUARTERS 4
#define C_PER_Q (C_CENTERS / QUARTERS)   // 64

__device__ __forceinline__ uint64_t pack2(float lo, float hi) {
    uint64_t r;
    asm("mov.b64 %0, {%1, %2};" : "=l"(r) : "f"(lo), "f"(hi));
    return r;
}
__device__ __forceinline__ void unpack2(uint64_t v, float& lo, float& hi) {
    asm("mov.b64 {%0, %1}, %2;" : "=f"(lo), "=f"(hi) : "l"(v));
}
__device__ __forceinline__ uint64_t fma2(uint64_t a, uint64_t b, uint64_t c) {
    uint64_t d;
    asm("fma.rn.f32x2 %0, %1, %2, %3;" : "=l"(d) : "l"(a), "l"(b), "l"(c));
    return d;
}
__device__ __forceinline__ uint64_t add2(uint64_t a, uint64_t b) {
    uint64_t d;
    asm("add.rn.f32x2 %0, %1, %2;" : "=l"(d) : "l"(a), "l"(b));
    return d;
}
__device__ __forceinline__ uint64_t mul2(uint64_t a, uint64_t b) {
    uint64_t d;
    asm("mul.rn.f32x2 %0, %1, %2;" : "=l"(d) : "l"(a), "l"(b));
    return d;
}
__device__ __forceinline__ float ex2_approx(float x) {
    float r;
    asm("ex2.approx.ftz.f32 %0, %1;" : "=f"(r) : "f"(x));
    return r;
}

__global__ void __launch_bounds__(TPB)
ensemble_rbf_kernel(const float* __restrict__ x,
                    const float* __restrict__ centers,
                    const float* __restrict__ weights,
                    float* __restrict__ out,
                    int n) {
    // Pre-packed broadcast tables. Each ulonglong2 = one LDS.128 delivering
    // two ready 64-bit packed f32x2 operands (no repacking MOVs).
    //   tabA[c] = { (gx,gx), (gy,gy) }       gx = 2*L2E*cx, gy = 2*L2E*cy
    //   tabB[c] = { (gz,gz), (w0x,w0y) }     gz = -L2E*|c|^2
    //   tabC[c] = { (w1x,w1y), (w2x,w2y) }
    //   tabD[c] = { (w3x,w3y), (w4x,w4y) }
    __shared__ ulonglong2 tabA[C_CENTERS];
    __shared__ ulonglong2 tabB[C_CENTERS];
    __shared__ ulonglong2 tabC[C_CENTERS];
    __shared__ ulonglong2 tabD[C_CENTERS];
    // Cross-quarter reduction buffer: quarters 1..3 publish 10 accs each.
    __shared__ uint64_t redbuf[3][M_MODELS * 2][PAIRS_PER_BLOCK];

    const int tid = threadIdx.x;
    const int lane = tid & (PAIRS_PER_BLOCK - 1);  // pair slot within block
    const int quarter = tid >> 5;                   // warp id = C quarter
    const float L2E = 1.4426950408889634f;

    // Stage tables: 2 centers per thread.
#pragma unroll
    for (int c = tid; c < C_CENTERS; c += TPB) {
        const float2 cc = reinterpret_cast<const float2*>(centers)[c];
        const float gx = 2.0f * L2E * cc.x;
        const float gy = 2.0f * L2E * cc.y;
        const float gz = -L2E * (cc.x * cc.x + cc.y * cc.y);
        const float2* w2 = reinterpret_cast<const float2*>(weights);
        const float2 a0 = w2[0 * C_CENTERS + c];
        const float2 a1 = w2[1 * C_CENTERS + c];
        const float2 a2 = w2[2 * C_CENTERS + c];
        const float2 a3 = w2[3 * C_CENTERS + c];
        const float2 a4 = w2[4 * C_CENTERS + c];
        tabA[c] = make_ulonglong2(pack2(gx, gx), pack2(gy, gy));
        tabB[c] = make_ulonglong2(pack2(gz, gz), pack2(a0.x, a0.y));
        tabC[c] = make_ulonglong2(pack2(a1.x, a1.y), pack2(a2.x, a2.y));
        tabD[c] = make_ulonglong2(pack2(a3.x, a3.y), pack2(a4.x, a4.y));
    }
    __syncthreads();

    const int pairIdx = blockIdx.x * PAIRS_PER_BLOCK + lane;
    const bool valid = (pairIdx * 2) < n;

    float4 xp = make_float4(0.0f, 0.0f, 0.0f, 0.0f);
    if (valid) xp = reinterpret_cast<const float4*>(x)[pairIdx];
    const float xx0 = xp.x, xy0 = xp.y, xx1 = xp.z, xy1 = xp.w;
    const uint64_t xxp = pack2(xx0, xx1);   // x-coords of both points
    const uint64_t xyp = pack2(xy0, xy1);   // y-coords of both points

    uint64_t acc[M_MODELS * 2];  // acc[m*2+p]: model m, point p, packed (d0,d1)
#pragma unroll
    for (int k = 0; k < M_MODELS * 2; k++) acc[k] = pack2(0.0f, 0.0f);

    const int cbase = quarter * C_PER_Q;

#pragma unroll 4
    for (int k = 0; k < C_PER_Q; k++) {
        const int c = cbase + k;
        const ulonglong2 A = tabA[c];
        const ulonglong2 B = tabB[c];
        const ulonglong2 Cq = tabC[c];
        const ulonglong2 Dq = tabD[c];

        // t = (t0,t1) for both points in one packed chain
        const uint64_t t = fma2(xxp, A.x, fma2(xyp, A.y, B.x));
        float t0, t1;
        unpack2(t, t0, t1);
        const float r0 = ex2_approx(t0);
        const float r1 = ex2_approx(t1);
        const uint64_t r0p = pack2(r0, r0);
        const uint64_t r1p = pack2(r1, r1);

        acc[0] = fma2(r0p, B.y, acc[0]);
        acc[1] = fma2(r1p, B.y, acc[1]);
        acc[2] = fma2(r0p, Cq.x, acc[2]);
        acc[3] = fma2(r1p, Cq.x, acc[3]);
        acc[4] = fma2(r0p, Cq.y, acc[4]);
        acc[5] = fma2(r1p, Cq.y, acc[5]);
        acc[6] = fma2(r0p, Dq.x, acc[6]);
        acc[7] = fma2(r1p, Dq.x, acc[7]);
        acc[8] = fma2(r0p, Dq.y, acc[8]);
        acc[9] = fma2(r1p, Dq.y, acc[9]);
    }

    // Quarters 1..3 publish partials; quarter 0 reduces + stores.
    if (quarter != 0) {
#pragma unroll
        for (int k = 0; k < M_MODELS * 2; k++) redbuf[quarter - 1][k][lane] = acc[k];
    }
    __syncthreads();

    if (quarter == 0 && valid) {
        // hoisted per-point scale: s = exp2(-L2E*|x|^2 - 4)  (sigma^2 folded in)
        const float s0 = ex2_approx(fmaf(fmaf(xx0, xx0, xy0 * xy0), -L2E, -4.0f));
        const float s1 = ex2_approx(fmaf(fmaf(xx1, xx1, xy1 * xy1), -L2E, -4.0f));
        const uint64_t s0p = pack2(s0, s0);
        const uint64_t s1p = pack2(s1, s1);

        const int i0 = pairIdx * 2;
#pragma unroll
        for (int m = 0; m < M_MODELS; m++) {
            uint64_t p0 = acc[m * 2 + 0];
            uint64_t p1 = acc[m * 2 + 1];
#pragma unroll
            for (int q = 0; q < 3; q++) {
                p0 = add2(p0, redbuf[q][m * 2 + 0][lane]);
                p1 = add2(p1, redbuf[q][m * 2 + 1][lane]);
            }
            p0 = mul2(p0, s0p);
            p1 = mul2(p1, s1p);
            float lo0, hi0, lo1, hi1;
            unpack2(p0, lo0, hi0);
            unpack2(p1, lo1, hi1);
            *reinterpret_cast<float4*>(out + (size_t)m * n * 2 + (size_t)i0 * 2) =
                make_float4(lo0, hi0, lo1, hi1);
        }
    }
}

extern "C" void kernel_launch(void* const* d_in, const int* in_sizes, int n_in,
                              void* d_out, int out_size) {
    const float* x = (const float*)d_in[0];        // [N, 2]
    const float* centers = (const float*)d_in[1];  // [256, 2]
    const float* weights = (const float*)d_in[2];  // [5, 256, 2]
    float* out = (float*)d_out;                    // [5, N, 2]

    const int n = in_sizes[0] / 2;
    const int pairs = n / 2;
    const int blocks = (pairs + PAIRS_PER_BLOCK - 1) / PAIRS_PER_BLOCK;
    ensemble_rbf_kernel<<<blocks, TPB>>>(x, centers, weights, out, n);
}

// round 6
// speedup vs baseline: 1.0917x; 1.0917x over previous
#include <cuda_runtime.h>
#include <cuda_bf16.h>
#include <cstdint>

// EnsembleRBF via legacy mma.sync (HMMA bf16, 3-pass hi/lo, fp32 accum).
// out[m,n,d] = sum_c exp(-||x_n-c||^2) * sigma^2 * W[m,c,d]
// N=100000, C=256, D=2, M=5.  GEMM view: A=[N,256] rbf, B=[256,16] Wt (10 used).
// exp2(t) with per-point factor exp2(-L2E|x|^2-4) hoisted to epilogue.

#define TPB 128
#define PTS_PER_WARP 16
#define PTS_PER_BLOCK 64
#define C_CENTERS 256
#define NSTEPS 16          // 256 / k16
#define CB_ST 65           // cbuf row stride (floats)

__device__ __forceinline__ float ex2a(float v) {
    float r; asm("ex2.approx.ftz.f32 %0, %1;" : "=f"(r) : "f"(v)); return r;
}
// pack {hi=a, lo=b} as bf16x2
__device__ __forceinline__ uint32_t bfpack(float hi, float lo) {
    uint32_t d;
    asm("cvt.rn.bf16x2.f32 %0, %1, %2;" : "=r"(d) : "f"(hi), "f"(lo));
    return d;
}
__device__ __forceinline__ float lo16f(uint32_t p) { return __uint_as_float(p << 16); }
__device__ __forceinline__ float hi16f(uint32_t p) { return __uint_as_float(p & 0xFFFF0000u); }

__device__ __forceinline__ void mma16816(float* c,
    uint32_t a0, uint32_t a1, uint32_t a2, uint32_t a3, uint32_t b0, uint32_t b1) {
    asm volatile(
        "mma.sync.aligned.m16n8k16.row.col.f32.bf16.bf16.f32 "
        "{%0,%1,%2,%3}, {%4,%5,%6,%7}, {%8,%9}, {%0,%1,%2,%3};"
        : "+f"(c[0]), "+f"(c[1]), "+f"(c[2]), "+f"(c[3])
        : "r"(a0), "r"(a1), "r"(a2), "r"(a3), "r"(b0), "r"(b1));
}

__global__ void __launch_bounds__(TPB)
rbf_mma_kernel(const float* __restrict__ x,
               const float* __restrict__ centers,
               const float* __restrict__ weights,
               float* __restrict__ out,
               int n) {
    // gtab[c] = (2*L2E*cx, 2*L2E*cy, -L2E*|c|^2, 0)
    __shared__ float4 gtab[C_CENTERS];                    // 4KB
    // B fragments, exact m16n8k16 col-major layout, hi and lo planes:
    // [step][lane] -> uint4 {t0b0, t0b1, t1b0, t1b1}
    __shared__ uint4 bfragH[NSTEPS * 32];                 // 8KB
    __shared__ uint4 bfragL[NSTEPS * 32];                 // 8KB
    __shared__ float cbuf[16 * CB_ST];                    // ~4KB epilogue transpose

    const int tid = threadIdx.x;
    const int lane = tid & 31;
    const int w = tid >> 5;
    const float L2E = 1.4426950408889634f;

    // ---- stage gtab ----
    for (int c = tid; c < C_CENTERS; c += TPB) {
        const float2 cc = reinterpret_cast<const float2*>(centers)[c];
        gtab[c] = make_float4(2.0f * L2E * cc.x, 2.0f * L2E * cc.y,
                              -L2E * (cc.x * cc.x + cc.y * cc.y), 0.0f);
    }
    // ---- stage B fragments (hi/lo bf16 split of W^T [256 x 16], cols>=10 zero) ----
    for (int e = tid; e < NSTEPS * 32; e += TPB) {
        const int s = e >> 5;
        const int l = e & 31;
        uint32_t hh[4], ll[4];
#pragma unroll
        for (int t = 0; t < 2; t++) {
#pragma unroll
            for (int b = 0; b < 2; b++) {
                const int j = t * 8 + (l >> 2);          // output column (2m+d)
                const int k = s * 16 + (l & 3) * 2 + b * 8;  // center index
                float w0 = 0.0f, w1 = 0.0f;
                if (j < 10) {
                    w0 = weights[(j >> 1) * 512 + k * 2 + (j & 1)];
                    w1 = weights[(j >> 1) * 512 + (k + 1) * 2 + (j & 1)];
                }
                const uint32_t hb0 = (uint32_t)__bfloat16_as_ushort(__float2bfloat16_rn(w0));
                const uint32_t hb1 = (uint32_t)__bfloat16_as_ushort(__float2bfloat16_rn(w1));
                const float r0 = w0 - __uint_as_float(hb0 << 16);
                const float r1 = w1 - __uint_as_float(hb1 << 16);
                const uint32_t lb0 = (uint32_t)__bfloat16_as_ushort(__float2bfloat16_rn(r0));
                const uint32_t lb1 = (uint32_t)__bfloat16_as_ushort(__float2bfloat16_rn(r1));
                hh[t * 2 + b] = hb0 | (hb1 << 16);
                ll[t * 2 + b] = lb0 | (lb1 << 16);
            }
        }
        bfragH[e] = make_uint4(hh[0], hh[1], hh[2], hh[3]);
        bfragL[e] = make_uint4(ll[0], ll[1], ll[2], ll[3]);
    }
    __syncthreads();

    // ---- per-lane A rows (points) ----
    const int pbase = blockIdx.x * PTS_PER_BLOCK + w * PTS_PER_WARP;
    const int p0 = pbase + (lane >> 2);
    const int p1 = p0 + 8;
    const int p0c = p0 < n ? p0 : (n - 1);
    const int p1c = p1 < n ? p1 : (n - 1);
    const float2 X0 = reinterpret_cast<const float2*>(x)[p0c];
    const float2 X1 = reinterpret_cast<const float2*>(x)[p1c];
    const int kb = (lane & 3) * 2;

    float cA[4] = {0.f, 0.f, 0.f, 0.f};   // n-tile 0 (cols 0-7)
    float cB[4] = {0.f, 0.f, 0.f, 0.f};   // n-tile 1 (cols 8-15)

#pragma unroll
    for (int s = 0; s < NSTEPS; s++) {
        const float4* gp = &gtab[s * 16 + kb];
        const float4 g0 = gp[0], g1 = gp[1], g2 = gp[8], g3 = gp[9];

        // 8 scores in fragment positions: t = 2L2E(x.c) - L2E|c|^2
        const float r00 = ex2a(fmaf(X0.x, g0.x, fmaf(X0.y, g0.y, g0.z)));
        const float r01 = ex2a(fmaf(X0.x, g1.x, fmaf(X0.y, g1.y, g1.z)));
        const float r02 = ex2a(fmaf(X0.x, g2.x, fmaf(X0.y, g2.y, g2.z)));
        const float r03 = ex2a(fmaf(X0.x, g3.x, fmaf(X0.y, g3.y, g3.z)));
        const float r10 = ex2a(fmaf(X1.x, g0.x, fmaf(X1.y, g0.y, g0.z)));
        const float r11 = ex2a(fmaf(X1.x, g1.x, fmaf(X1.y, g1.y, g1.z)));
        const float r12 = ex2a(fmaf(X1.x, g2.x, fmaf(X1.y, g2.y, g2.z)));
        const float r13 = ex2a(fmaf(X1.x, g3.x, fmaf(X1.y, g3.y, g3.z)));

        // hi packs: {lo-half = even k, hi-half = odd k}
        const uint32_t a0h = bfpack(r01, r00);
        const uint32_t a1h = bfpack(r11, r10);
        const uint32_t a2h = bfpack(r03, r02);
        const uint32_t a3h = bfpack(r13, r12);
        // residuals -> lo packs
        const uint32_t a0l = bfpack(r01 - hi16f(a0h), r00 - lo16f(a0h));
        const uint32_t a1l = bfpack(r11 - hi16f(a1h), r10 - lo16f(a1h));
        const uint32_t a2l = bfpack(r03 - hi16f(a2h), r02 - lo16f(a2h));
        const uint32_t a3l = bfpack(r13 - hi16f(a3h), r12 - lo16f(a3h));

        const uint4 BH = bfragH[s * 32 + lane];
        const uint4 BL = bfragL[s * 32 + lane];

        // tile 0
        mma16816(cA, a0h, a1h, a2h, a3h, BH.x, BH.y);  // Ah*Bh
        mma16816(cA, a0h, a1h, a2h, a3h, BL.x, BL.y);  // Ah*Bl
        mma16816(cA, a0l, a1l, a2l, a3l, BH.x, BH.y);  // Al*Bh
        // tile 1
        mma16816(cB, a0h, a1h, a2h, a3h, BH.z, BH.w);
        mma16816(cB, a0h, a1h, a2h, a3h, BL.z, BL.w);
        mma16816(cB, a0l, a1l, a2l, a3l, BH.z, BH.w);
    }

    // ---- epilogue: per-point scale, transpose via smem, coalesced stores ----
    const float s0 = ex2a(fmaf(fmaf(X0.x, X0.x, X0.y * X0.y), -L2E, -4.0f));
    const float s1 = ex2a(fmaf(fmaf(X1.x, X1.x, X1.y * X1.y), -L2E, -4.0f));

    const int pl0 = w * PTS_PER_WARP + (lane >> 2);
    const int pl1 = pl0 + 8;
    const int j0 = (lane & 3) * 2;
    cbuf[(j0 + 0) * CB_ST + pl0] = cA[0] * s0;
    cbuf[(j0 + 1) * CB_ST + pl0] = cA[1] * s0;
    cbuf[(j0 + 0) * CB_ST + pl1] = cA[2] * s1;
    cbuf[(j0 + 1) * CB_ST + pl1] = cA[3] * s1;
    cbuf[(j0 + 8) * CB_ST + pl0] = cB[0] * s0;
    cbuf[(j0 + 9) * CB_ST + pl0] = cB[1] * s0;
    cbuf[(j0 + 8) * CB_ST + pl1] = cB[2] * s1;
    cbuf[(j0 + 9) * CB_ST + pl1] = cB[3] * s1;
    __syncthreads();

    const int gbase = blockIdx.x * PTS_PER_BLOCK;
#pragma unroll
    for (int e = tid; e < 5 * PTS_PER_BLOCK; e += TPB) {
        const int m = e >> 6;       // 0..4
        const int p = e & 63;
        const int gp = gbase + p;
        if (gp < n) {
            const float2 v = make_float2(cbuf[(2 * m + 0) * CB_ST + p],
                                         cbuf[(2 * m + 1) * CB_ST + p]);
            *reinterpret_cast<float2*>(out + (size_t)m * n * 2 + (size_t)gp * 2) = v;
        }
    }
}

extern "C" void kernel_launch(void* const* d_in, const int* in_sizes, int n_in,
                              void* d_out, int out_size) {
    const float* x = (const float*)d_in[0];        // [N, 2]
    const float* centers = (const float*)d_in[1];  // [256, 2]
    const float* weights = (const float*)d_in[2];  // [5, 256, 2]
    float* out = (float*)d_out;                    // [5, N, 2]

    const int n = in_sizes[0] / 2;
    const int blocks = (n + PTS_PER_BLOCK - 1) / PTS_PER_BLOCK;
    rbf_mma_kernel<<<blocks, TPB>>>(x, centers, weights, out, n);
}

// round 7
// speedup vs baseline: 1.4147x; 1.2959x over previous
#include <cuda_runtime.h>
#include <cuda_fp16.h>
#include <cstdint>

// EnsembleRBF via mma.sync m16n8k16 fp16 (2-pass: A single fp16, B hi+lo fp16).
// out[m,n,d] = sum_c exp(-||x_n-c||^2) * sigma^2 * W[m,c,d]
// N=100000, C=256, D=2, M=5.
// A[n,c] = exp2(-L2E*d^2 - 4) computed in fragment positions (bias folded ->
// r in (0, 2^-4], fp16-safe). 32 points/warp (two m16 tiles sharing B/g loads).

#define TPB 128
#define PTS_PER_BLOCK 128
#define C_CENTERS 256
#define NSTEPS 16
#define CB_ST 130

__device__ __forceinline__ float ex2a(float v) {
    float r; asm("ex2.approx.ftz.f32 %0, %1;" : "=f"(r) : "f"(v)); return r;
}
// pack {upper=a, lower=b} as f16x2
__device__ __forceinline__ uint32_t hpack(float a, float b) {
    uint32_t d;
    asm("cvt.rn.f16x2.f32 %0, %1, %2;" : "=r"(d) : "f"(a), "f"(b));
    return d;
}

__device__ __forceinline__ void mma16816(float* c,
    uint32_t a0, uint32_t a1, uint32_t a2, uint32_t a3, uint32_t b0, uint32_t b1) {
    asm volatile(
        "mma.sync.aligned.m16n8k16.row.col.f32.f16.f16.f32 "
        "{%0,%1,%2,%3}, {%4,%5,%6,%7}, {%8,%9}, {%0,%1,%2,%3};"
        : "+f"(c[0]), "+f"(c[1]), "+f"(c[2]), "+f"(c[3])
        : "r"(a0), "r"(a1), "r"(a2), "r"(a3), "r"(b0), "r"(b1));
}

__global__ void __launch_bounds__(TPB)
rbf_mma_kernel(const float* __restrict__ x,
               const float* __restrict__ centers,
               const float* __restrict__ weights,
               float* __restrict__ out,
               int n) {
    // gtab[c] = (2*L2E*cx, 2*L2E*cy, -L2E*|c|^2, 0)
    __shared__ float4 gtab[C_CENTERS];                 // 4KB
    // B fragments [step][lane] -> uint4 {n0b0, n0b1, n1b0, n1b1}, hi & lo planes
    __shared__ uint4 bfragH[NSTEPS * 32];              // 8KB
    __shared__ uint4 bfragL[NSTEPS * 32];              // 8KB
    __shared__ float cbuf[16 * CB_ST];                 // 8.1KB epilogue transpose

    const int tid = threadIdx.x;
    const int lane = tid & 31;
    const int w = tid >> 5;
    const float L2E = 1.4426950408889634f;

    // ---- stage gtab ----
    for (int c = tid; c < C_CENTERS; c += TPB) {
        const float2 cc = reinterpret_cast<const float2*>(centers)[c];
        gtab[c] = make_float4(2.0f * L2E * cc.x, 2.0f * L2E * cc.y,
                              -L2E * (cc.x * cc.x + cc.y * cc.y), 0.0f);
    }
    // ---- stage B fragments: W^T [256 x 16] (cols >= 10 zero), fp16 hi + lo ----
    for (int e = tid; e < NSTEPS * 32; e += TPB) {
        const int s = e >> 5;
        const int l = e & 31;
        uint32_t hh[4], ll[4];
#pragma unroll
        for (int t = 0; t < 2; t++) {
#pragma unroll
            for (int b = 0; b < 2; b++) {
                const int j = t * 8 + (l >> 2);              // output column (2m+d)
                const int k = s * 16 + (l & 3) * 2 + b * 8;  // center index
                float w0 = 0.0f, w1 = 0.0f;
                if (j < 10) {
                    w0 = weights[(j >> 1) * 512 + k * 2 + (j & 1)];
                    w1 = weights[(j >> 1) * 512 + (k + 1) * 2 + (j & 1)];
                }
                const __half h0 = __float2half_rn(w0);
                const __half h1 = __float2half_rn(w1);
                const float r0 = w0 - __half2float(h0);
                const float r1 = w1 - __half2float(h1);
                const __half l0 = __float2half_rn(r0);
                const __half l1 = __float2half_rn(r1);
                hh[t * 2 + b] = (uint32_t)__half_as_ushort(h0) |
                                ((uint32_t)__half_as_ushort(h1) << 16);
                ll[t * 2 + b] = (uint32_t)__half_as_ushort(l0) |
                                ((uint32_t)__half_as_ushort(l1) << 16);
            }
        }
        bfragH[e] = make_uint4(hh[0], hh[1], hh[2], hh[3]);
        bfragL[e] = make_uint4(ll[0], ll[1], ll[2], ll[3]);
    }
    __syncthreads();

    // ---- 4 points per lane: tile A rows (pA0, pA0+8), tile B rows (+16, +24) ----
    const int gbase = blockIdx.x * PTS_PER_BLOCK;
    const int lp = w * 32 + (lane >> 2);
    const int q0 = gbase + lp;
    const int q1 = q0 + 8;
    const int q2 = q0 + 16;
    const int q3 = q0 + 24;
    const float2 XA0 = reinterpret_cast<const float2*>(x)[q0 < n ? q0 : (n - 1)];
    const float2 XA1 = reinterpret_cast<const float2*>(x)[q1 < n ? q1 : (n - 1)];
    const float2 XB0 = reinterpret_cast<const float2*>(x)[q2 < n ? q2 : (n - 1)];
    const float2 XB1 = reinterpret_cast<const float2*>(x)[q3 < n ? q3 : (n - 1)];
    // per-point bias: -L2E*|x|^2 - 4  (sigma^2 = 2^-4 folded)
    const float tA0 = fmaf(fmaf(XA0.x, XA0.x, XA0.y * XA0.y), -L2E, -4.0f);
    const float tA1 = fmaf(fmaf(XA1.x, XA1.x, XA1.y * XA1.y), -L2E, -4.0f);
    const float tB0 = fmaf(fmaf(XB0.x, XB0.x, XB0.y * XB0.y), -L2E, -4.0f);
    const float tB1 = fmaf(fmaf(XB1.x, XB1.x, XB1.y * XB1.y), -L2E, -4.0f);

    const int kb = (lane & 3) * 2;

    float cA0[4] = {0.f, 0.f, 0.f, 0.f};  // tile A, cols 0-7
    float cA1[4] = {0.f, 0.f, 0.f, 0.f};  // tile A, cols 8-15
    float cB0[4] = {0.f, 0.f, 0.f, 0.f};  // tile B, cols 0-7
    float cB1[4] = {0.f, 0.f, 0.f, 0.f};  // tile B, cols 8-15

#pragma unroll
    for (int s = 0; s < NSTEPS; s++) {
        const float4* gp = &gtab[s * 16 + kb];
        const float4 g0 = gp[0], g1 = gp[1], g2 = gp[8], g3 = gp[9];

        // scores r = exp2(x.gx + y.gy + gz + tb), fragment positions
        const float rA00 = ex2a(fmaf(XA0.x, g0.x, fmaf(XA0.y, g0.y, g0.z)) + tA0);
        const float rA01 = ex2a(fmaf(XA0.x, g1.x, fmaf(XA0.y, g1.y, g1.z)) + tA0);
        const float rA02 = ex2a(fmaf(XA0.x, g2.x, fmaf(XA0.y, g2.y, g2.z)) + tA0);
        const float rA03 = ex2a(fmaf(XA0.x, g3.x, fmaf(XA0.y, g3.y, g3.z)) + tA0);
        const float rA10 = ex2a(fmaf(XA1.x, g0.x, fmaf(XA1.y, g0.y, g0.z)) + tA1);
        const float rA11 = ex2a(fmaf(XA1.x, g1.x, fmaf(XA1.y, g1.y, g1.z)) + tA1);
        const float rA12 = ex2a(fmaf(XA1.x, g2.x, fmaf(XA1.y, g2.y, g2.z)) + tA1);
        const float rA13 = ex2a(fmaf(XA1.x, g3.x, fmaf(XA1.y, g3.y, g3.z)) + tA1);
        const float rB00 = ex2a(fmaf(XB0.x, g0.x, fmaf(XB0.y, g0.y, g0.z)) + tB0);
        const float rB01 = ex2a(fmaf(XB0.x, g1.x, fmaf(XB0.y, g1.y, g1.z)) + tB0);
        const float rB02 = ex2a(fmaf(XB0.x, g2.x, fmaf(XB0.y, g2.y, g2.z)) + tB0);
        const float rB03 = ex2a(fmaf(XB0.x, g3.x, fmaf(XB0.y, g3.y, g3.z)) + tB0);
        const float rB10 = ex2a(fmaf(XB1.x, g0.x, fmaf(XB1.y, g0.y, g0.z)) + tB1);
        const float rB11 = ex2a(fmaf(XB1.x, g1.x, fmaf(XB1.y, g1.y, g1.z)) + tB1);
        const float rB12 = ex2a(fmaf(XB1.x, g2.x, fmaf(XB1.y, g2.y, g2.z)) + tB1);
        const float rB13 = ex2a(fmaf(XB1.x, g3.x, fmaf(XB1.y, g3.y, g3.z)) + tB1);

        // A fragments: {upper = k+1 col, lower = k col}
        const uint32_t aA0 = hpack(rA01, rA00);
        const uint32_t aA1 = hpack(rA11, rA10);
        const uint32_t aA2 = hpack(rA03, rA02);
        const uint32_t aA3 = hpack(rA13, rA12);
        const uint32_t aB0 = hpack(rB01, rB00);
        const uint32_t aB1 = hpack(rB11, rB10);
        const uint32_t aB2 = hpack(rB03, rB02);
        const uint32_t aB3 = hpack(rB13, rB12);

        const uint4 BH = bfragH[s * 32 + lane];
        const uint4 BL = bfragL[s * 32 + lane];

        mma16816(cA0, aA0, aA1, aA2, aA3, BH.x, BH.y);
        mma16816(cA0, aA0, aA1, aA2, aA3, BL.x, BL.y);
        mma16816(cA1, aA0, aA1, aA2, aA3, BH.z, BH.w);
        mma16816(cA1, aA0, aA1, aA2, aA3, BL.z, BL.w);
        mma16816(cB0, aB0, aB1, aB2, aB3, BH.x, BH.y);
        mma16816(cB0, aB0, aB1, aB2, aB3, BL.x, BL.y);
        mma16816(cB1, aB0, aB1, aB2, aB3, BH.z, BH.w);
        mma16816(cB1, aB0, aB1, aB2, aB3, BL.z, BL.w);
    }

    // ---- epilogue: transpose via smem, coalesced float2 stores ----
    const int j0 = (lane & 3) * 2;
    const int pA0 = lp, pA1 = lp + 8, pB0 = lp + 16, pB1 = lp + 24;
    cbuf[(j0 + 0) * CB_ST + pA0] = cA0[0];
    cbuf[(j0 + 1) * CB_ST + pA0] = cA0[1];
    cbuf[(j0 + 0) * CB_ST + pA1] = cA0[2];
    cbuf[(j0 + 1) * CB_ST + pA1] = cA0[3];
    cbuf[(j0 + 8) * CB_ST + pA0] = cA1[0];
    cbuf[(j0 + 9) * CB_ST + pA0] = cA1[1];
    cbuf[(j0 + 8) * CB_ST + pA1] = cA1[2];
    cbuf[(j0 + 9) * CB_ST + pA1] = cA1[3];
    cbuf[(j0 + 0) * CB_ST + pB0] = cB0[0];
    cbuf[(j0 + 1) * CB_ST + pB0] = cB0[1];
    cbuf[(j0 + 0) * CB_ST + pB1] = cB0[2];
    cbuf[(j0 + 1) * CB_ST + pB1] = cB0[3];
    cbuf[(j0 + 8) * CB_ST + pB0] = cB1[0];
    cbuf[(j0 + 9) * CB_ST + pB0] = cB1[1];
    cbuf[(j0 + 8) * CB_ST + pB1] = cB1[2];
    cbuf[(j0 + 9) * CB_ST + pB1] = cB1[3];
    __syncthreads();

#pragma unroll
    for (int e = tid; e < 5 * PTS_PER_BLOCK; e += TPB) {
        const int m = e >> 7;      // 0..4
        const int p = e & 127;
        const int gp = gbase + p;
        if (gp < n) {
            const float2 v = make_float2(cbuf[(2 * m + 0) * CB_ST + p],
                                         cbuf[(2 * m + 1) * CB_ST + p]);
            *reinterpret_cast<float2*>(out + (size_t)m * n * 2 + (size_t)gp * 2) = v;
        }
    }
}

extern "C" void kernel_launch(void* const* d_in, const int* in_sizes, int n_in,
                              void* d_out, int out_size) {
    const float* x = (const float*)d_in[0];        // [N, 2]
    const float* centers = (const float*)d_in[1];  // [256, 2]
    const float* weights = (const float*)d_in[2];  // [5, 256, 2]
    float* out = (float*)d_out;                    // [5, N, 2]

    const int n = in_sizes[0] / 2;
    const int blocks = (n + PTS_PER_BLOCK - 1) / PTS_PER_BLOCK;
    rbf_mma_kernel<<<blocks, TPB>>>(x, centers, weights, out, n);
}